// round 1
// baseline (speedup 1.0000x reference)
#include <cuda_runtime.h>
#include <math.h>

// Problem constants: B=16, C=256, H=W=32
#define PNUM 16384          // total pixels
#define CNUM 256
#define NKTOT 2304          // 9*C
#define CLIP1 0.9999999f    // 1 - 1e-7 artanh clip
#define MAXN  0.99999f      // 1 - 1e-5 ball projection
#define EPSF  1e-15f

// ---------------- device scratch (static, no allocations) ----------------
__device__ float g_v [PNUM*CNUM];   // logmap0(x)*scale (conv input), reused for conv2
__device__ float g_mm[PNUM*CNUM];   // raw conv output
__device__ float g_h [PNUM*CNUM];   // post-FC ball points (bn input), reused
__device__ float g_q2[PNUM];        // per-pixel ||v||^2
__device__ float g_s [PNUM];        // per-pixel lam*alpha
__device__ float g_zn[512];         // column norms of z1 (0..255) and z2 (256..511)
__device__ float g_pm[128*CNUM];    // bn partial: sum lam*x
__device__ float g_pd[128];         // bn partial: sum (lam-1)
__device__ float g_pv[128];         // bn partial: sum dist^2
__device__ float g_mu[CNUM];        // gyromidpoint
__device__ float g_sc[8];           // {mu2, lam_mu, b2, lam_b, <b,mu>, rstd}

// ---------------- block reduction (blockDim == 256) ----------------
template<int K>
__device__ __forceinline__ void blockReduceK(float* v, float* sbuf) {
    int tid = threadIdx.x, lane = tid & 31, wid = tid >> 5;
#pragma unroll
    for (int i = 0; i < K; i++) {
        float x = v[i];
#pragma unroll
        for (int o = 16; o > 0; o >>= 1) x += __shfl_down_sync(0xffffffffu, x, o);
        if (lane == 0) sbuf[i*8 + wid] = x;
    }
    __syncthreads();
    if (tid == 0) {
#pragma unroll
        for (int i = 0; i < K; i++) {
            float s = sbuf[i*8];
            for (int w = 1; w < 8; w++) s += sbuf[i*8 + w];
            sbuf[i*8] = s;
        }
    }
    __syncthreads();
#pragma unroll
    for (int i = 0; i < K; i++) v[i] = sbuf[i*8];
    __syncthreads();
}

// ---------------- z column norms ----------------
__global__ void zn_kernel(const float* __restrict__ z1, const float* __restrict__ z2) {
    int col = blockIdx.x;                    // 0..511
    const float* z = (col < 256) ? z1 : z2;
    int j = col & 255;
    float s = 0.f;
    for (int k = threadIdx.x; k < NKTOT; k += 64) {
        float w = z[k*256 + j];
        s += w*w;
    }
#pragma unroll
    for (int o = 16; o > 0; o >>= 1) s += __shfl_down_sync(0xffffffffu, s, o);
    __shared__ float sb[2];
    if ((threadIdx.x & 31) == 0) sb[threadIdx.x >> 5] = s;
    __syncthreads();
    if (threadIdx.x == 0) g_zn[col] = sqrtf(fmaxf(sb[0] + sb[1], EPSF));
}

// ---------------- pre: x [B,C,H,W] -> v=logmap0(x)*scale [P,C] + q2 ----------------
__global__ void pre_kernel(const float* __restrict__ x, float scale) {
    __shared__ float sb[8];
    int p = blockIdx.x, c = threadIdx.x;
    int b = p >> 10, hw = p & 1023;
    float xv = x[(size_t)(b*256 + c)*1024 + hw];
    float r[1] = { xv*xv };
    blockReduceK<1>(r, sb);
    float n = sqrtf(fmaxf(r[0], EPSF));
    float f = atanhf(fminf(n, CLIP1)) / n * scale;
    g_v[(size_t)p*256 + c] = f*xv;
    if (c == 0) g_q2[p] = f*f*r[0];
}

// ---------------- per-pixel s = lam*alpha from 3x3 q2 sums ----------------
__global__ void s_kernel() {
    int p = blockIdx.x*256 + threadIdx.x;
    int h = (p >> 5) & 31, w = p & 31;
    float np2 = 0.f;
#pragma unroll
    for (int dy = -1; dy <= 1; dy++)
#pragma unroll
        for (int dx = -1; dx <= 1; dx++) {
            int sh = h + dy, sw = w + dx;
            if ((unsigned)sh < 32u && (unsigned)sw < 32u) np2 += g_q2[p + dy*32 + dx];
        }
    float np = sqrtf(fmaxf(np2, EPSF));
    float th = tanhf(np);
    float uf = th / np;          // factor mapping patches -> u
    float un = th;               // ||u|| before projection
    if (un > MAXN) { uf *= MAXN/un; un = MAXN; }
    float lam = 2.0f / fmaxf(1.0f - un*un, EPSF);
    g_s[p] = lam * uf;
}

// ---------------- implicit 3x3 conv as fp32 GEMM: g_mm = unfold(g_v) @ z ----------------
// M=16384 (pixels), K=2304 (9 taps x 256), N=256. Tile 128x64, BK=16, 256 thr, 8x4/thread.
__global__ void __launch_bounds__(256) conv_kernel(const float* __restrict__ z) {
    __shared__ float As[16][132];
    __shared__ float Bs[16][64];
    int p0 = blockIdx.x * 128;
    int j0 = blockIdx.y * 64;
    int tid = threadIdx.x;
    int lk   = tid & 15;     // loader: k within chunk
    int lm0  = tid >> 4;     // loader: row base (stride 16)
    int trow = tid >> 4;     // compute: rows trow*8..+7
    int tcol = tid & 15;     // compute: cols tcol*4..+3
    float acc[8][4];
#pragma unroll
    for (int i = 0; i < 8; i++)
#pragma unroll
        for (int j = 0; j < 4; j++) acc[i][j] = 0.f;

    int hh[8], ww[8];
#pragma unroll
    for (int r = 0; r < 8; r++) {
        int p = p0 + lm0 + r*16;
        hh[r] = (p >> 5) & 31;
        ww[r] = p & 31;
    }

    for (int tap = 0; tap < 9; tap++) {
        int ty = tap/3 - 1, tx = tap%3 - 1;
        int dpo = ty*32 + tx;
        bool ok[8];
        const float* vb[8];
#pragma unroll
        for (int r = 0; r < 8; r++) {
            int sh = hh[r] + ty, sw = ww[r] + tx;
            ok[r] = ((unsigned)sh < 32u) && ((unsigned)sw < 32u);
            vb[r] = g_v + (size_t)(p0 + lm0 + r*16 + dpo)*256;
        }
        const float* zb = z + (size_t)(tap*256)*256 + j0;
        for (int cb = 0; cb < 256; cb += 16) {
#pragma unroll
            for (int r = 0; r < 8; r++)
                As[lk][lm0 + r*16] = ok[r] ? vb[r][cb + lk] : 0.f;
#pragma unroll
            for (int r = 0; r < 4; r++) {
                int kk = (tid >> 6) + r*4;
                Bs[kk][tid & 63] = zb[(size_t)(cb + kk)*256 + (tid & 63)];
            }
            __syncthreads();
#pragma unroll
            for (int kk = 0; kk < 16; kk++) {
                float4 a0 = *(const float4*)&As[kk][trow*8];
                float4 a1 = *(const float4*)&As[kk][trow*8 + 4];
                float4 b  = *(const float4*)&Bs[kk][tcol*4];
                float a[8] = {a0.x,a0.y,a0.z,a0.w,a1.x,a1.y,a1.z,a1.w};
                float bb[4] = {b.x,b.y,b.z,b.w};
#pragma unroll
                for (int i = 0; i < 8; i++)
#pragma unroll
                    for (int j = 0; j < 4; j++) acc[i][j] += a[i]*bb[j];
            }
            __syncthreads();
        }
    }
#pragma unroll
    for (int i = 0; i < 8; i++) {
        int p = p0 + trow*8 + i;
        float4 o = make_float4(acc[i][0], acc[i][1], acc[i][2], acc[i][3]);
        *(float4*)&g_mm[(size_t)p*256 + j0 + tcol*4] = o;
    }
}

// ---------------- Poincare FC epilogue ----------------
__global__ void fc_kernel(int znoff) {
    __shared__ float sb[8];
    int p = blockIdx.x, j = threadIdx.x;
    float s = g_s[p];
    float zn = g_zn[znoff + j];
    float t = g_mm[(size_t)p*256 + j] * s / zn;
    float d = 2.0f * zn * asinhf(t);
    float y = sinhf(d);
    float r[1] = { y*y };
    blockReduceK<1>(r, sb);
    g_h[(size_t)p*256 + j] = y / (1.0f + sqrtf(1.0f + r[0]));
}

// ---------------- BN phase 1: partial sums of lam*x and (lam-1) ----------------
__global__ void bnred_kernel() {
    __shared__ float sb[8];
    int c = threadIdx.x;
    float accm = 0.f, accd = 0.f;
    int p0 = blockIdx.x * 128;
    for (int i = 0; i < 128; i++) {
        float xv = g_h[(size_t)(p0 + i)*256 + c];
        float r[1] = { xv*xv };
        blockReduceK<1>(r, sb);
        float lam = 2.0f / fmaxf(1.0f - r[0], EPSF);
        accm += lam*xv;
        accd += lam - 1.0f;
    }
    g_pm[blockIdx.x*256 + c] = accm;
    if (c == 0) g_pd[blockIdx.x] = accd;
}

// ---------------- BN phase 2: gyromidpoint mu + scalars ----------------
__global__ void bnmu_kernel(const float* __restrict__ bias) {
    __shared__ float sb[24];
    int c = threadIdx.x;
    float msum = 0.f;
    for (int g = 0; g < 128; g++) msum += g_pm[g*256 + c];
    float dv = (c < 128) ? g_pd[c] : 0.f;
    float r1[1] = { dv };
    blockReduceK<1>(r1, sb);
    float den = fmaxf(r1[0], EPSF);
    float m = msum / den;
    float r2[1] = { m*m };
    blockReduceK<1>(r2, sb);
    float nm = sqrtf(fmaxf(r2[0], EPSF));
    float fac = tanhf(0.5f * atanhf(fminf(nm, CLIP1))) / nm;
    float muc = fac * m;
    g_mu[c] = muc;
    float bc = bias[c];
    float r3[3] = { muc*muc, bc*bc, bc*muc };
    blockReduceK<3>(r3, sb);
    if (c == 0) {
        float mu2 = r3[0], b2 = r3[1], bm = r3[2];
        g_sc[0] = mu2;
        g_sc[1] = 2.0f / fmaxf(1.0f - mu2, EPSF);
        g_sc[2] = b2;
        g_sc[3] = 2.0f / fmaxf(1.0f - b2, EPSF);
        g_sc[4] = bm;
    }
}

// ---------------- BN phase 3: partial variance ----------------
__global__ void bnvar_kernel() {
    __shared__ float sb[16];
    int c = threadIdx.x;
    float muc = g_mu[c];
    float mu2 = g_sc[0];
    float acc = 0.f;
    int p0 = blockIdx.x * 128;
    for (int i = 0; i < 128; i++) {
        float xv = g_h[(size_t)(p0 + i)*256 + c];
        float r[2] = { xv*xv, xv*muc };
        blockReduceK<2>(r, sb);
        float xp2 = r[0], ip = r[1];
        float A = 1.0f - 2.0f*ip + mu2;   // coef on (-x) in mobius_add(-x, mu)
        float B = 1.0f - xp2;             // coef on mu
        float nn = fmaxf(A*A*xp2 - 2.0f*A*B*ip + B*B*mu2, 0.f);
        float den = fmaxf(1.0f - 2.0f*ip + xp2*mu2, EPSF);
        float nr = sqrtf(fmaxf(nn/(den*den), EPSF));
        float dd = 2.0f * atanhf(fminf(nr, CLIP1));
        acc += dd*dd;
    }
    if (c == 0) g_pv[blockIdx.x] = acc;
}

// ---------------- BN phase 4: finalize rstd ----------------
__global__ void bnfin_kernel(const float* __restrict__ weight) {
    int tid = threadIdx.x;               // 128 threads
    float v = g_pv[tid];
#pragma unroll
    for (int o = 16; o > 0; o >>= 1) v += __shfl_down_sync(0xffffffffu, v, o);
    __shared__ float sb[4];
    if ((tid & 31) == 0) sb[tid >> 5] = v;
    __syncthreads();
    if (tid == 0) {
        float var = (sb[0] + sb[1] + sb[2] + sb[3]) / 16384.0f;
        g_sc[5] = sqrtf(weight[0] / fmaxf(var, EPSF));
    }
}

// ---------------- shared BN point transform: returns h (post-project) and ||h|| ----------------
__device__ __forceinline__ void bn_point(float xv, float muc, float bc, float* sb,
                                         float& hc, float& nh) {
    float mu2 = g_sc[0], lam_mu = g_sc[1], b2 = g_sc[2], lam_b = g_sc[3],
          bm = g_sc[4], rstd = g_sc[5];
    float r3[3] = { xv*xv, muc*xv, bc*xv };
    blockReduceK<3>(r3, sb);
    float xp2 = r3[0], ip = r3[1], bx = r3[2];
    // v = logmap(mu, x)
    float A  = 1.0f - 2.0f*ip + xp2;     // coef on (-mu) in mobius_add(-mu, x)
    float Bc = 1.0f - mu2;               // coef on x
    float den = fmaxf(1.0f - 2.0f*ip + mu2*xp2, EPSF);
    float dv = (Bc*xv - A*muc) / den;
    float nd2 = fmaxf(A*A*mu2 - 2.0f*A*Bc*ip + Bc*Bc*xp2, 0.f) / (den*den);
    float nd = sqrtf(fmaxf(nd2, EPSF));
    float cv = (2.0f/lam_mu) * atanhf(fminf(nd, CLIP1)) / nd;
    float vc = cv * dv;
    // u = transp(mu, bias, v) * rstd : gyration(bias, -mu, v) * lam_mu/lam_b
    float uw = cv * (Bc*bx - A*bm) / den;     // <bias, v>
    float vw = cv * (A*mu2 - Bc*ip) / den;    // <-mu, v>
    float av  = -uw*mu2 - vw - 2.0f*bm*vw;
    float bv2 = -vw*b2 + uw;
    float dgy = fmaxf(1.0f - 2.0f*bm + b2*mu2, EPSF);
    float gyr = vc + 2.0f*(av*bc - bv2*muc) / dgy;
    float uc = gyr * (lam_mu / lam_b) * rstd;
    // h = project(expmap(bias, u))
    float r2[2] = { uc*uc, bc*uc };
    blockReduceK<2>(r2, sb);
    float nu = sqrtf(fmaxf(r2[0], EPSF));
    float tf = tanhf(0.5f * lam_b * nu) / nu;
    float sec = tf * uc;
    float s2m = tf*tf*r2[0];
    float bs  = tf*r2[1];
    float A3 = 1.0f + 2.0f*bs + s2m, B3 = 1.0f - b2;
    float den3 = fmaxf(1.0f + 2.0f*bs + b2*s2m, EPSF);
    hc = (A3*bc + B3*sec) / den3;
    float nh2 = fmaxf(A3*A3*b2 + 2.0f*A3*B3*bs + B3*B3*s2m, 0.f) / (den3*den3);
    nh = sqrtf(fmaxf(nh2, EPSF));
    if (nh > MAXN) { hc *= MAXN/nh; nh = MAXN; }
}

// ---------------- BN apply + hrelu + pre-for-conv2 (fused) ----------------
__global__ void bnapply_kernel(const float* __restrict__ bias, float scale) {
    __shared__ float sb[24];
    int p = blockIdx.x, c = threadIdx.x;
    float xv = g_h[(size_t)p*256 + c];
    float muc = g_mu[c], bc = bias[c];
    float hc, nh;
    bn_point(xv, muc, bc, sb, hc, nh);
    // hrelu
    float lf = atanhf(fminf(nh, CLIP1)) / nh;
    float rc = fmaxf(lf*hc, 0.f);
    float r1[1] = { rc*rc };
    blockReduceK<1>(r1, sb);
    float nr = sqrtf(fmaxf(r1[0], EPSF));
    float ef = tanhf(nr) / nr;
    float hrc = ef * rc;
    float nhr = sqrtf(fmaxf(ef*ef*r1[0], EPSF));
    if (nhr > MAXN) { hrc *= MAXN/nhr; nhr = MAXN; }
    // pre: logmap0 * scale for next conv
    float f3 = atanhf(fminf(nhr, CLIP1)) / nhr * scale;
    g_v[(size_t)p*256 + c] = f3 * hrc;
    if (c == 0) g_q2[p] = f3*f3*nhr*nhr;
}

// ---------------- BN2 apply + residual mobius_add + hrelu + transpose out ----------------
__global__ void final_kernel(const float* __restrict__ bias, const float* __restrict__ xin,
                             float* __restrict__ out) {
    __shared__ float sb[24];
    int p = blockIdx.x, c = threadIdx.x;
    int b = p >> 10, hw = p & 1023;
    float xv = g_h[(size_t)p*256 + c];
    float muc = g_mu[c], bc = bias[c];
    float hc, nh;
    bn_point(xv, muc, bc, sb, hc, nh);
    // residual: mobius_add(h, res)
    float resc = xin[(size_t)(b*256 + c)*1024 + hw];
    float rr[2] = { resc*resc, hc*resc };
    blockReduceK<2>(rr, sb);
    float y2 = rr[0], xy = rr[1];
    float x2 = nh*nh;
    float A4 = 1.0f + 2.0f*xy + y2, B4 = 1.0f - x2;
    float den4 = fmaxf(1.0f + 2.0f*xy + x2*y2, EPSF);
    float hm = (A4*hc + B4*resc) / den4;
    float nm2 = fmaxf(A4*A4*x2 + 2.0f*A4*B4*xy + B4*B4*y2, 0.f) / (den4*den4);
    float nmv = sqrtf(fmaxf(nm2, EPSF));
    // hrelu
    float lf = atanhf(fminf(nmv, CLIP1)) / nmv;
    float rc = fmaxf(lf*hm, 0.f);
    float r1[1] = { rc*rc };
    blockReduceK<1>(r1, sb);
    float nr = sqrtf(fmaxf(r1[0], EPSF));
    float ef = tanhf(nr) / nr;
    float oc = ef * rc;
    float nhr = sqrtf(fmaxf(ef*ef*r1[0], EPSF));
    if (nhr > MAXN) oc *= MAXN/nhr;
    out[(size_t)(b*256 + c)*1024 + hw] = oc;
}

// ---------------- launcher ----------------
extern "C" void kernel_launch(void* const* d_in, const int* in_sizes, int n_in,
                              void* d_out, int out_size) {
    const float* x  = (const float*)d_in[0];
    const float* z1 = (const float*)d_in[1];
    const float* z2 = (const float*)d_in[2];
    const float* w1 = (const float*)d_in[3];
    const float* b1 = (const float*)d_in[4];
    const float* w2 = (const float*)d_in[5];
    const float* b2 = (const float*)d_in[6];
    float* out = (float*)d_out;

    // scale = Beta(1152, 0.5) / Beta(128, 0.5)
    double lg = lgamma(1152.0) - lgamma(1152.5) - lgamma(128.0) + lgamma(128.5);
    float scale = (float)exp(lg);

    dim3 cgrid(128, 4);

    zn_kernel<<<512, 64>>>(z1, z2);
    pre_kernel<<<PNUM, 256>>>(x, scale);
    s_kernel<<<64, 256>>>();
    conv_kernel<<<cgrid, 256>>>(z1);
    fc_kernel<<<PNUM, 256>>>(0);

    bnred_kernel<<<128, 256>>>();
    bnmu_kernel<<<1, 256>>>(b1);
    bnvar_kernel<<<128, 256>>>();
    bnfin_kernel<<<1, 128>>>(w1);
    bnapply_kernel<<<PNUM, 256>>>(b1, scale);

    s_kernel<<<64, 256>>>();
    conv_kernel<<<cgrid, 256>>>(z2);
    fc_kernel<<<PNUM, 256>>>(256);

    bnred_kernel<<<128, 256>>>();
    bnmu_kernel<<<1, 256>>>(b2);
    bnvar_kernel<<<128, 256>>>();
    bnfin_kernel<<<1, 128>>>(w2);
    final_kernel<<<PNUM, 256>>>(b2, x, out);
}

// round 3
// speedup vs baseline: 3.0671x; 3.0671x over previous
#include <cuda_runtime.h>
#include <cuda_bf16.h>
#include <math.h>
#include <stdint.h>

// Problem constants: B=16, C=256, H=W=32
#define PNUM 16384
#define CNUM 256
#define NKTOT 2304
#define CLIP1 0.9999999f
#define MAXN  0.99999f
#define EPSF  1e-15f

#define PADP  (16*1156)          // padded pixels: 16 x 34 x 34
#define STAGE_BYTES 49152        // Ahi 8K + Alo 8K + Bhi 16K + Blo 16K
#define YST   264                // ybuf row stride (floats)
#define CONV_SMEM (128*YST*4)    // 135168 >= 2*STAGE_BYTES

// ---------------- device scratch ----------------
__device__ __align__(16) __nv_bfloat16 g_vhi[PADP*CNUM];
__device__ __align__(16) __nv_bfloat16 g_vlo[PADP*CNUM];
__device__ __align__(16) __nv_bfloat16 g_zthi1[CNUM*NKTOT];
__device__ __align__(16) __nv_bfloat16 g_ztlo1[CNUM*NKTOT];
__device__ __align__(16) __nv_bfloat16 g_zthi2[CNUM*NKTOT];
__device__ __align__(16) __nv_bfloat16 g_ztlo2[CNUM*NKTOT];
__device__ __align__(16) float g_h [PNUM*CNUM];
__device__ float g_q2[PNUM];
__device__ float g_s [PNUM];
__device__ float g_zn[512];
__device__ float g_pm[128*CNUM];
__device__ float g_pd[128];
__device__ float g_pv[128];
__device__ float g_mu[CNUM];
__device__ float g_sc[8];

// ---------------- PTX helpers (all baseline compute_103-safe) ----------------
__device__ __forceinline__ uint32_t smem_u32(const void* p) {
    uint32_t a;
    asm("{ .reg .u64 t; cvta.to.shared.u64 t, %1; cvt.u32.u64 %0, t; }" : "=r"(a) : "l"(p));
    return a;
}
__device__ __forceinline__ void cpa16(uint32_t dst, const void* src) {
    asm volatile("cp.async.cg.shared.global [%0], [%1], 16;" :: "r"(dst), "l"(src) : "memory");
}
__device__ __forceinline__ void cp_commit() {
    asm volatile("cp.async.commit_group;" ::: "memory");
}
template<int N>
__device__ __forceinline__ void cp_wait() {
    asm volatile("cp.async.wait_group %0;" :: "n"(N) : "memory");
}
__device__ __forceinline__ void ldsm4(uint32_t* r, uint32_t addr) {
    asm volatile("ldmatrix.sync.aligned.m8n8.x4.shared.b16 {%0,%1,%2,%3}, [%4];"
        : "=r"(r[0]), "=r"(r[1]), "=r"(r[2]), "=r"(r[3]) : "r"(addr));
}
__device__ __forceinline__ void mma16816(float* d, const uint32_t* a, const uint32_t* b) {
    asm volatile("mma.sync.aligned.m16n8k16.row.col.f32.bf16.bf16.f32 "
        "{%0,%1,%2,%3}, {%4,%5,%6,%7}, {%8,%9}, {%0,%1,%2,%3};"
        : "+f"(d[0]), "+f"(d[1]), "+f"(d[2]), "+f"(d[3])
        : "r"(a[0]), "r"(a[1]), "r"(a[2]), "r"(a[3]), "r"(b[0]), "r"(b[1]));
}

// swizzled physical offset within a [rows][32 bf16] tile (row = 64B, chunk = 16B)
__device__ __forceinline__ uint32_t swz(int r, int c) {
    return (uint32_t)(((r >> 1) << 7) | (((((r & 1) << 2) | c) ^ ((r >> 1) & 7)) << 4));
}

// ---------------- reductions ----------------
__device__ __forceinline__ float warpSum(float v) {
#pragma unroll
    for (int o = 16; o > 0; o >>= 1) v += __shfl_xor_sync(0xffffffffu, v, o);
    return v;
}
template<int K>
__device__ __forceinline__ void blockReduceK(float* v, float* sbuf) {
    int tid = threadIdx.x, lane = tid & 31, wid = tid >> 5;
#pragma unroll
    for (int i = 0; i < K; i++) {
        float x = v[i];
#pragma unroll
        for (int o = 16; o > 0; o >>= 1) x += __shfl_down_sync(0xffffffffu, x, o);
        if (lane == 0) sbuf[i*8 + wid] = x;
    }
    __syncthreads();
    if (tid == 0) {
#pragma unroll
        for (int i = 0; i < K; i++) {
            float s = sbuf[i*8];
            for (int w = 1; w < 8; w++) s += sbuf[i*8 + w];
            sbuf[i*8] = s;
        }
    }
    __syncthreads();
#pragma unroll
    for (int i = 0; i < K; i++) v[i] = sbuf[i*8];
    __syncthreads();
}

// ---------------- bf16 split store ----------------
union BU { uint4 u; __nv_bfloat16 h[8]; };
__device__ __forceinline__ void store_split8(size_t base, const float* v) {
    BU hi, lo;
#pragma unroll
    for (int i = 0; i < 8; i++) {
        __nv_bfloat16 h = __float2bfloat16(v[i]);
        hi.h[i] = h;
        lo.h[i] = __float2bfloat16(v[i] - __bfloat162float(h));
    }
    *(uint4*)(g_vhi + base) = hi.u;
    *(uint4*)(g_vlo + base) = lo.u;
}

// ---------------- zero padded borders ----------------
__global__ void zb_kernel() {
    int wid = threadIdx.x >> 5, lid = threadIdx.x & 31;
    int p = blockIdx.x * 8 + wid;
    if (p >= PADP) return;
    int pp = p % 1156, hh = pp / 34, ww = pp % 34;
    if (hh == 0 || hh == 33 || ww == 0 || ww == 33) {
        size_t base = (size_t)p * 256 + lid * 8;
        uint4 z = make_uint4(0u, 0u, 0u, 0u);
        *(uint4*)(g_vhi + base) = z;
        *(uint4*)(g_vlo + base) = z;
    }
}

// ---------------- z column norms ----------------
__global__ void zn_kernel(const float* __restrict__ z1, const float* __restrict__ z2) {
    int col = blockIdx.x;
    const float* z = (col < 256) ? z1 : z2;
    int j = col & 255;
    float s = 0.f;
    for (int k = threadIdx.x; k < NKTOT; k += 64) {
        float w = z[k*256 + j];
        s += w*w;
    }
#pragma unroll
    for (int o = 16; o > 0; o >>= 1) s += __shfl_down_sync(0xffffffffu, s, o);
    __shared__ float sb[2];
    if ((threadIdx.x & 31) == 0) sb[threadIdx.x >> 5] = s;
    __syncthreads();
    if (threadIdx.x == 0) g_zn[col] = sqrtf(fmaxf(sb[0] + sb[1], EPSF));
}

// ---------------- z split + transpose: z[K,N] fp32 -> zT hi/lo [N,K] bf16 ----------------
__global__ void zsplit_kernel(const float* __restrict__ z1, const float* __restrict__ z2) {
    __shared__ float t[32][33];
    const float* z = blockIdx.z ? z2 : z1;
    __nv_bfloat16* oh = blockIdx.z ? g_zthi2 : g_zthi1;
    __nv_bfloat16* ol = blockIdx.z ? g_ztlo2 : g_ztlo1;
    int kb = blockIdx.x * 32, nb = blockIdx.y * 32;
    int tx = threadIdx.x, ty = threadIdx.y;
#pragma unroll
    for (int i = 0; i < 4; i++)
        t[ty + i*8][tx] = z[(size_t)(kb + ty + i*8)*256 + nb + tx];
    __syncthreads();
#pragma unroll
    for (int i = 0; i < 4; i++) {
        int n = nb + ty + i*8, k = kb + tx;
        float v = t[tx][ty + i*8];
        __nv_bfloat16 h = __float2bfloat16(v);
        oh[(size_t)n*NKTOT + k] = h;
        ol[(size_t)n*NKTOT + k] = __float2bfloat16(v - __bfloat162float(h));
    }
}

// ---------------- pre: x NCHW -> padded v hi/lo + q2 (warp-per-pixel) ----------------
__global__ void pre_w(const float* __restrict__ x, float scale) {
    int wid = threadIdx.x >> 5, lid = threadIdx.x & 31;
    int p = blockIdx.x * 8 + wid;
    int b = p >> 10, hw = p & 1023, h = (p >> 5) & 31, w = p & 31;
    float xv[8];
#pragma unroll
    for (int i = 0; i < 8; i++)
        xv[i] = x[(size_t)(b*256 + lid*8 + i)*1024 + hw];
    float q = 0.f;
#pragma unroll
    for (int i = 0; i < 8; i++) q += xv[i]*xv[i];
    float n2 = warpSum(q);
    float n = sqrtf(fmaxf(n2, EPSF));
    float f = atanhf(fminf(n, CLIP1)) / n * scale;
    float vv[8];
#pragma unroll
    for (int i = 0; i < 8; i++) vv[i] = f * xv[i];
    size_t base = ((size_t)(b*1156 + (h+1)*34 + (w+1)))*256 + lid*8;
    store_split8(base, vv);
    if (lid == 0) g_q2[p] = f*f*n2;
}

// ---------------- per-pixel s = lam*alpha from 3x3 q2 sums ----------------
__global__ void s_kernel() {
    int p = blockIdx.x*256 + threadIdx.x;
    int h = (p >> 5) & 31, w = p & 31;
    float np2 = 0.f;
#pragma unroll
    for (int dy = -1; dy <= 1; dy++)
#pragma unroll
        for (int dx = -1; dx <= 1; dx++) {
            int sh = h + dy, sw = w + dx;
            if ((unsigned)sh < 32u && (unsigned)sw < 32u) np2 += g_q2[p + dy*32 + dx];
        }
    float np = sqrtf(fmaxf(np2, EPSF));
    float th = tanhf(np);
    float uf = th / np;
    float un = th;
    if (un > MAXN) { uf *= MAXN/un; un = MAXN; }
    float lam = 2.0f / fmaxf(1.0f - un*un, EPSF);
    g_s[p] = lam * uf;
}

// ---------------- HMMA conv + fused Poincare-FC epilogue ----------------
// CTA: 128 pixels (M) x 256 outputs (N). 512 thr = 16 warps (4m x 4n), warp 32x64.
// K = 9 taps x 256 ch, bf16 split-3 (hi*hi + lo*hi + hi*lo), fp32 accum. BK=32.
__global__ void __launch_bounds__(512, 1) conv_mma(int which) {
    extern __shared__ __align__(16) char dsm[];
    uint32_t sbase = smem_u32(dsm);

    const __nv_bfloat16* zThi = which ? g_zthi2 : g_zthi1;
    const __nv_bfloat16* zTlo = which ? g_ztlo2 : g_ztlo1;
    int znoff = which ? 256 : 0;

    int tid = threadIdx.x, wid = tid >> 5, l = tid & 31;
    int p0 = blockIdx.x << 7;
    int b  = blockIdx.x >> 3;
    int h0 = (blockIdx.x & 7) << 2;

    // ---- loader precompute ----
    int lr = tid >> 2, lc = tid & 3;                       // A chunk: row, 16B-chunk
    int aIdx0 = (b*1156 + (h0 + (lr >> 5) + 1)*34 + ((lr & 31) + 1))*256 + lc*8;
    uint32_t physA = swz(lr, lc);
    int bn0 = tid >> 2, bn1 = (tid + 512) >> 2;            // B rows for i=0,1
    int bIdx0 = bn0*NKTOT + lc*8;
    int bIdx1 = bn1*NKTOT + ((tid + 512) & 3)*8;
    uint32_t physB0 = swz(bn0, lc);
    uint32_t physB1 = swz(bn1, (tid + 512) & 3);

    // ---- mma lane precompute ----
    int m0 = (wid & 3) << 5;
    int n0 = (wid >> 2) << 6;
    {
    }
    int mi = l >> 3;
    int rA = m0 + ((mi & 1) << 3) + (l & 7);
    uint32_t qA0 = swz(rA, mi >> 1);                       // cA folded in
    int rB = n0 + (((mi >> 1) & 1) << 3) + (l & 7);
    uint32_t qB0 = swz(rB, mi & 1);                        // cB folded in

    float acc[2][8][4];
#pragma unroll
    for (int i = 0; i < 2; i++)
#pragma unroll
        for (int j = 0; j < 8; j++)
#pragma unroll
            for (int k = 0; k < 4; k++) acc[i][j][k] = 0.f;

    // ---- issue chunk loads ----
    auto load_chunk = [&](int kc, int stage) {
        int tap = kc >> 3;
        int dy = (tap * 11) >> 5;                          // tap/3 for tap<9
        int dx = tap - dy*3;
        int cb = (kc & 7) << 5;
        int ad = ((dy - 1)*34 + (dx - 1))*256 + cb;
        int bd = tap*256 + cb;
        uint32_t st = sbase + stage*STAGE_BYTES;
        cpa16(st + physA,             g_vhi + (aIdx0 + ad));
        cpa16(st + 8192  + physA,     g_vlo + (aIdx0 + ad));
        cpa16(st + 16384 + physB0,    zThi + (bIdx0 + bd));
        cpa16(st + 32768 + physB0,    zTlo + (bIdx0 + bd));
        cpa16(st + 16384 + physB1,    zThi + (bIdx1 + bd));
        cpa16(st + 32768 + physB1,    zTlo + (bIdx1 + bd));
        cp_commit();
    };

    load_chunk(0, 0);

    for (int kc = 0; kc < 72; kc++) {
        int stage = kc & 1;
        if (kc < 71) { load_chunk(kc + 1, stage ^ 1); cp_wait<1>(); }
        else cp_wait<0>();
        __syncthreads();

        uint32_t sA_hi = sbase + stage*STAGE_BYTES;
        uint32_t sA_lo = sA_hi + 8192;
        uint32_t sB_hi = sA_hi + 16384;
        uint32_t sB_lo = sA_hi + 32768;

        uint32_t a[8], bb[16];
#pragma unroll
        for (int ks = 0; ks < 2; ks++) {
            uint32_t kx = (uint32_t)(ks << 5);
            uint32_t qa = qA0 ^ kx, qb = qB0 ^ kx;
            // A hi, B hi -> hihi
            ldsm4(a,     sA_hi + qa);
            ldsm4(a + 4, sA_hi + qa + 1024);
#pragma unroll
            for (int j = 0; j < 4; j++) ldsm4(bb + j*4, sB_hi + qb + j*1024);
#pragma unroll
            for (int mf = 0; mf < 2; mf++)
#pragma unroll
                for (int nf = 0; nf < 8; nf++)
                    mma16816(acc[mf][nf], a + mf*4, bb + nf*2);
            // A lo x B hi -> lohi
            ldsm4(a,     sA_lo + qa);
            ldsm4(a + 4, sA_lo + qa + 1024);
#pragma unroll
            for (int mf = 0; mf < 2; mf++)
#pragma unroll
                for (int nf = 0; nf < 8; nf++)
                    mma16816(acc[mf][nf], a + mf*4, bb + nf*2);
            // A hi x B lo -> hilo
            ldsm4(a,     sA_hi + qa);
            ldsm4(a + 4, sA_hi + qa + 1024);
#pragma unroll
            for (int j = 0; j < 4; j++) ldsm4(bb + j*4, sB_lo + qb + j*1024);
#pragma unroll
            for (int mf = 0; mf < 2; mf++)
#pragma unroll
                for (int nf = 0; nf < 8; nf++)
                    mma16816(acc[mf][nf], a + mf*4, bb + nf*2);
        }
        __syncthreads();
    }

    // ---- fused Poincare-FC epilogue ----
    float* ybuf = (float*)dsm;
    int row0 = m0 + (l >> 2);
    int col0 = n0 + ((l & 3) << 1);
    float sr[2][2];
#pragma unroll
    for (int mf = 0; mf < 2; mf++)
#pragma unroll
        for (int hf = 0; hf < 2; hf++)
            sr[mf][hf] = g_s[p0 + row0 + mf*16 + hf*8];
    float2 zn2[8];
#pragma unroll
    for (int nf = 0; nf < 8; nf++)
        zn2[nf] = *(const float2*)&g_zn[znoff + col0 + nf*8];

#pragma unroll
    for (int mf = 0; mf < 2; mf++)
#pragma unroll
        for (int nf = 0; nf < 8; nf++)
#pragma unroll
            for (int hf = 0; hf < 2; hf++) {
                float s = sr[mf][hf];
                float z0 = zn2[nf].x, z1 = zn2[nf].y;
                float a0 = acc[mf][nf][hf*2], a1 = acc[mf][nf][hf*2 + 1];
                float y0 = sinhf(2.0f*z0*asinhf(a0*s/z0));
                float y1 = sinhf(2.0f*z1*asinhf(a1*s/z1));
                int r = row0 + mf*16 + hf*8;
                *(float2*)&ybuf[r*YST + col0 + nf*8] = make_float2(y0, y1);
            }
    __syncthreads();

    // row reduction + scale + write g_h
    {
        int row = tid >> 2, q = tid & 3;
        const float4* yr = (const float4*)(ybuf + row*YST + q*64);
        float tot = 0.f;
#pragma unroll
        for (int i = 0; i < 16; i++) {
            float4 v = yr[i];
            tot += v.x*v.x + v.y*v.y + v.z*v.z + v.w*v.w;
        }
        tot += __shfl_xor_sync(0xffffffffu, tot, 1);
        tot += __shfl_xor_sync(0xffffffffu, tot, 2);
        float inv = 1.0f / (1.0f + sqrtf(1.0f + tot));
        float4* dst = (float4*)(g_h + (size_t)(p0 + row)*256 + q*64);
#pragma unroll
        for (int i = 0; i < 16; i++) {
            float4 v = yr[i];
            v.x *= inv; v.y *= inv; v.z *= inv; v.w *= inv;
            dst[i] = v;
        }
    }
}

// ---------------- BN phase 1: partial sums (warp-per-pixel) ----------------
__global__ void bnred_w() {
    __shared__ float sm[8][256];
    __shared__ float sd[8];
    int wid = threadIdx.x >> 5, lid = threadIdx.x & 31;
    int p0 = blockIdx.x * 128;
    float accm[8] = {0,0,0,0,0,0,0,0};
    float accd = 0.f;
    for (int i = 0; i < 16; i++) {
        int p = p0 + wid*16 + i;
        const float4* row = (const float4*)(g_h + (size_t)p*256 + lid*8);
        float4 a = row[0], c = row[1];
        float v[8] = {a.x,a.y,a.z,a.w,c.x,c.y,c.z,c.w};
        float q = 0.f;
#pragma unroll
        for (int j = 0; j < 8; j++) q += v[j]*v[j];
        float n2 = warpSum(q);
        float lam = 2.0f / fmaxf(1.0f - n2, EPSF);
#pragma unroll
        for (int j = 0; j < 8; j++) accm[j] += lam * v[j];
        accd += lam - 1.0f;
    }
#pragma unroll
    for (int j = 0; j < 8; j++) sm[wid][lid*8 + j] = accm[j];
    if (lid == 0) sd[wid] = accd;
    __syncthreads();
    int c = threadIdx.x;
    float s = 0.f;
    for (int w = 0; w < 8; w++) s += sm[w][c];
    g_pm[blockIdx.x*256 + c] = s;
    if (c == 0) {
        float d = 0.f;
        for (int w = 0; w < 8; w++) d += sd[w];
        g_pd[blockIdx.x] = d;
    }
}

// ---------------- BN phase 2: gyromidpoint + scalars ----------------
__global__ void bnmu_kernel(const float* __restrict__ bias) {
    __shared__ float sb[24];
    int c = threadIdx.x;
    float msum = 0.f;
    for (int g = 0; g < 128; g++) msum += g_pm[g*256 + c];
    float dv = (c < 128) ? g_pd[c] : 0.f;
    float r1[1] = { dv };
    blockReduceK<1>(r1, sb);
    float den = fmaxf(r1[0], EPSF);
    float m = msum / den;
    float r2[1] = { m*m };
    blockReduceK<1>(r2, sb);
    float nm = sqrtf(fmaxf(r2[0], EPSF));
    float fac = tanhf(0.5f * atanhf(fminf(nm, CLIP1))) / nm;
    float muc = fac * m;
    g_mu[c] = muc;
    float bc = bias[c];
    float r3[3] = { muc*muc, bc*bc, bc*muc };
    blockReduceK<3>(r3, sb);
    if (c == 0) {
        float mu2 = r3[0], b2 = r3[1], bm = r3[2];
        g_sc[0] = mu2;
        g_sc[1] = 2.0f / fmaxf(1.0f - mu2, EPSF);
        g_sc[2] = b2;
        g_sc[3] = 2.0f / fmaxf(1.0f - b2, EPSF);
        g_sc[4] = bm;
    }
}

// ---------------- BN phase 3: partial variance (warp-per-pixel) ----------------
__global__ void bnvar_w() {
    __shared__ float sv[8];
    int wid = threadIdx.x >> 5, lid = threadIdx.x & 31;
    int p0 = blockIdx.x * 128;
    float mu8[8];
#pragma unroll
    for (int j = 0; j < 8; j++) mu8[j] = g_mu[lid*8 + j];
    float mu2 = g_sc[0];
    float acc = 0.f;
    for (int i = 0; i < 16; i++) {
        int p = p0 + wid*16 + i;
        const float4* row = (const float4*)(g_h + (size_t)p*256 + lid*8);
        float4 a = row[0], cc = row[1];
        float v[8] = {a.x,a.y,a.z,a.w,cc.x,cc.y,cc.z,cc.w};
        float q1 = 0.f, q2 = 0.f;
#pragma unroll
        for (int j = 0; j < 8; j++) { q1 += v[j]*v[j]; q2 += v[j]*mu8[j]; }
        float xp2 = warpSum(q1);
        float ip  = warpSum(q2);
        float A = 1.0f - 2.0f*ip + mu2;
        float B = 1.0f - xp2;
        float nn = fmaxf(A*A*xp2 - 2.0f*A*B*ip + B*B*mu2, 0.f);
        float den = fmaxf(1.0f - 2.0f*ip + xp2*mu2, EPSF);
        float nr = sqrtf(fmaxf(nn/(den*den), EPSF));
        float dd = 2.0f * atanhf(fminf(nr, CLIP1));
        acc += dd*dd;
    }
    if (lid == 0) sv[wid] = acc;
    __syncthreads();
    if (threadIdx.x == 0) {
        float s = 0.f;
        for (int w = 0; w < 8; w++) s += sv[w];
        g_pv[blockIdx.x] = s;
    }
}

// ---------------- BN phase 4: finalize rstd ----------------
__global__ void bnfin_kernel(const float* __restrict__ weight) {
    int tid = threadIdx.x;
    float v = g_pv[tid];
#pragma unroll
    for (int o = 16; o > 0; o >>= 1) v += __shfl_down_sync(0xffffffffu, v, o);
    __shared__ float sb[4];
    if ((tid & 31) == 0) sb[tid >> 5] = v;
    __syncthreads();
    if (tid == 0) {
        float var = (sb[0] + sb[1] + sb[2] + sb[3]) / 16384.0f;
        g_sc[5] = sqrtf(weight[0] / fmaxf(var, EPSF));
    }
}

// ---------------- shared BN point transform (warp version) ----------------
__device__ __forceinline__ float bn_point_w(const float* xv, const float* mu8, const float* b8,
                                            float* hc) {
    float mu2 = g_sc[0], lam_mu = g_sc[1], b2 = g_sc[2], lam_b = g_sc[3],
          bm = g_sc[4], rstd = g_sc[5];
    float s0 = 0.f, s1 = 0.f, s2 = 0.f;
#pragma unroll
    for (int i = 0; i < 8; i++) { s0 += xv[i]*xv[i]; s1 += mu8[i]*xv[i]; s2 += b8[i]*xv[i]; }
    float xp2 = warpSum(s0), ip = warpSum(s1), bx = warpSum(s2);
    float A  = 1.0f - 2.0f*ip + xp2;
    float Bc = 1.0f - mu2;
    float den = fmaxf(1.0f - 2.0f*ip + mu2*xp2, EPSF);
    float nd2 = fmaxf(A*A*mu2 - 2.0f*A*Bc*ip + Bc*Bc*xp2, 0.f) / (den*den);
    float nd = sqrtf(fmaxf(nd2, EPSF));
    float cv = (2.0f/lam_mu) * atanhf(fminf(nd, CLIP1)) / nd;
    float uw = cv * (Bc*bx - A*bm) / den;
    float vw = cv * (A*mu2 - Bc*ip) / den;
    float av  = -uw*mu2 - vw - 2.0f*bm*vw;
    float bv2 = -vw*b2 + uw;
    float dgy = fmaxf(1.0f - 2.0f*bm + b2*mu2, EPSF);
    float fac = (lam_mu / lam_b) * rstd;
    float uc[8];
    float t0 = 0.f, t1 = 0.f;
#pragma unroll
    for (int i = 0; i < 8; i++) {
        float vc = cv * (Bc*xv[i] - A*mu8[i]) / den;
        uc[i] = (vc + 2.0f*(av*b8[i] - bv2*mu8[i]) / dgy) * fac;
        t0 += uc[i]*uc[i];
        t1 += b8[i]*uc[i];
    }
    float u2 = warpSum(t0), bu = warpSum(t1);
    float nu = sqrtf(fmaxf(u2, EPSF));
    float tf = tanhf(0.5f * lam_b * nu) / nu;
    float s2m = tf*tf*u2;
    float bs  = tf*bu;
    float A3 = 1.0f + 2.0f*bs + s2m, B3 = 1.0f - b2;
    float den3 = fmaxf(1.0f + 2.0f*bs + b2*s2m, EPSF);
#pragma unroll
    for (int i = 0; i < 8; i++) hc[i] = (A3*b8[i] + B3*tf*uc[i]) / den3;
    float nh2 = fmaxf(A3*A3*b2 + 2.0f*A3*B3*bs + B3*B3*s2m, 0.f) / (den3*den3);
    float nh = sqrtf(fmaxf(nh2, EPSF));
    if (nh > MAXN) {
        float q = MAXN / nh;
#pragma unroll
        for (int i = 0; i < 8; i++) hc[i] *= q;
        nh = MAXN;
    }
    return nh;
}

// ---------------- BN apply + hrelu + pre-for-conv2 (warp-per-pixel) ----------------
__global__ void bnapply_w(const float* __restrict__ bias, float scale) {
    int wid = threadIdx.x >> 5, lid = threadIdx.x & 31;
    int p = blockIdx.x * 8 + wid;
    int b = p >> 10, h = (p >> 5) & 31, w = p & 31;
    const float4* row = (const float4*)(g_h + (size_t)p*256 + lid*8);
    float4 a = row[0], cc = row[1];
    float xv[8] = {a.x,a.y,a.z,a.w,cc.x,cc.y,cc.z,cc.w};
    float mu8[8], b8[8];
#pragma unroll
    for (int j = 0; j < 8; j++) { mu8[j] = g_mu[lid*8 + j]; b8[j] = bias[lid*8 + j]; }
    float hc[8];
    float nh = bn_point_w(xv, mu8, b8, hc);
    float lf = atanhf(fminf(nh, CLIP1)) / nh;
    float rc[8];
    float q = 0.f;
#pragma unroll
    for (int i = 0; i < 8; i++) { rc[i] = fmaxf(lf*hc[i], 0.f); q += rc[i]*rc[i]; }
    float rs = warpSum(q);
    float nr = sqrtf(fmaxf(rs, EPSF));
    float ef = tanhf(nr) / nr;
    float nhr = sqrtf(fmaxf(ef*ef*rs, EPSF));
    float adj = 1.0f;
    if (nhr > MAXN) { adj = MAXN/nhr; nhr = MAXN; }
    float f3 = atanhf(fminf(nhr, CLIP1)) / nhr * scale;
    float vv[8];
#pragma unroll
    for (int i = 0; i < 8; i++) vv[i] = f3 * ef * adj * rc[i];
    size_t base = ((size_t)(b*1156 + (h+1)*34 + (w+1)))*256 + lid*8;
    store_split8(base, vv);
    if (lid == 0) g_q2[p] = f3*f3*nhr*nhr;
}

// ---------------- BN2 apply + residual + hrelu + NCHW out ----------------
__global__ void final_w(const float* __restrict__ bias, const float* __restrict__ xin,
                        float* __restrict__ out) {
    int wid = threadIdx.x >> 5, lid = threadIdx.x & 31;
    int p = blockIdx.x * 8 + wid;
    int b = p >> 10, hw = p & 1023;
    const float4* row = (const float4*)(g_h + (size_t)p*256 + lid*8);
    float4 a = row[0], cc = row[1];
    float xv[8] = {a.x,a.y,a.z,a.w,cc.x,cc.y,cc.z,cc.w};
    float mu8[8], b8[8];
#pragma unroll
    for (int j = 0; j < 8; j++) { mu8[j] = g_mu[lid*8 + j]; b8[j] = bias[lid*8 + j]; }
    float hc[8];
    float nh = bn_point_w(xv, mu8, b8, hc);
    float res[8];
    float q1 = 0.f, q2 = 0.f;
#pragma unroll
    for (int i = 0; i < 8; i++) {
        res[i] = xin[(size_t)(b*256 + lid*8 + i)*1024 + hw];
        q1 += res[i]*res[i];
        q2 += hc[i]*res[i];
    }
    float y2 = warpSum(q1), xy = warpSum(q2);
    float x2 = nh*nh;
    float A4 = 1.0f + 2.0f*xy + y2, B4 = 1.0f - x2;
    float den4 = fmaxf(1.0f + 2.0f*xy + x2*y2, EPSF);
    float hm[8];
#pragma unroll
    for (int i = 0; i < 8; i++) hm[i] = (A4*hc[i] + B4*res[i]) / den4;
    float nm2 = fmaxf(A4*A4*x2 + 2.0f*A4*B4*xy + B4*B4*y2, 0.f) / (den4*den4);
    float nmv = sqrtf(fmaxf(nm2, EPSF));
    float lf = atanhf(fminf(nmv, CLIP1)) / nmv;
    float rc[8];
    float q = 0.f;
#pragma unroll
    for (int i = 0; i < 8; i++) { rc[i] = fmaxf(lf*hm[i], 0.f); q += rc[i]*rc[i]; }
    float rs = warpSum(q);
    float nr = sqrtf(fmaxf(rs, EPSF));
    float ef = tanhf(nr) / nr;
    float nhr = sqrtf(fmaxf(ef*ef*rs, EPSF));
    float adj = (nhr > MAXN) ? MAXN/nhr : 1.0f;
#pragma unroll
    for (int i = 0; i < 8; i++)
        out[(size_t)(b*256 + lid*8 + i)*1024 + hw] = ef * adj * rc[i];
}

// ---------------- launcher ----------------
extern "C" void kernel_launch(void* const* d_in, const int* in_sizes, int n_in,
                              void* d_out, int out_size) {
    const float* x  = (const float*)d_in[0];
    const float* z1 = (const float*)d_in[1];
    const float* z2 = (const float*)d_in[2];
    const float* w1 = (const float*)d_in[3];
    const float* b1 = (const float*)d_in[4];
    const float* w2 = (const float*)d_in[5];
    const float* b2 = (const float*)d_in[6];
    float* out = (float*)d_out;

    // scale = Beta(1152, 0.5) / Beta(128, 0.5)
    double lg = lgamma(1152.0) - lgamma(1152.5) - lgamma(128.0) + lgamma(128.5);
    float scale = (float)exp(lg);

    static int smem_set = 0;
    if (!smem_set) {
        cudaFuncSetAttribute(conv_mma, cudaFuncAttributeMaxDynamicSharedMemorySize, CONV_SMEM);
        smem_set = 1;
    }

    zb_kernel<<<(PADP + 7)/8, 256>>>();
    zn_kernel<<<512, 64>>>(z1, z2);
    zsplit_kernel<<<dim3(72, 8, 2), dim3(32, 8)>>>(z1, z2);
    pre_w<<<PNUM/8, 256>>>(x, scale);
    s_kernel<<<64, 256>>>();
    conv_mma<<<128, 512, CONV_SMEM>>>(0);

    bnred_w<<<128, 256>>>();
    bnmu_kernel<<<1, 256>>>(b1);
    bnvar_w<<<128, 256>>>();
    bnfin_kernel<<<1, 128>>>(w1);
    bnapply_w<<<PNUM/8, 256>>>(b1, scale);

    s_kernel<<<64, 256>>>();
    conv_mma<<<128, 512, CONV_SMEM>>>(1);

    bnred_w<<<128, 256>>>();
    bnmu_kernel<<<1, 256>>>(b2);
    bnvar_w<<<128, 256>>>();
    bnfin_kernel<<<1, 128>>>(w2);
    final_w<<<PNUM/8, 256>>>(b2, x, out);
}

// round 4
// speedup vs baseline: 3.1783x; 1.0363x over previous
#include <cuda_runtime.h>
#include <cuda_bf16.h>
#include <math.h>
#include <stdint.h>

// Problem constants: B=16, C=256, H=W=32
#define PNUM 16384
#define CNUM 256
#define NKTOT 2304
#define CLIP1 0.9999999f
#define MAXN  0.99999f
#define EPSF  1e-15f

#define PADP  (16*1156)          // padded pixels: 16 x 34 x 34
#define STAGE_BYTES 49152        // Ahi 8K + Alo 8K + Bhi 16K + Blo 16K
#define YST   264                // ybuf row stride (floats)
#define CONV_SMEM (3*STAGE_BYTES) // 147456 >= ybuf 135168

// ---------------- device scratch ----------------
__device__ __align__(16) __nv_bfloat16 g_vhi[PADP*CNUM];
__device__ __align__(16) __nv_bfloat16 g_vlo[PADP*CNUM];
__device__ __align__(16) __nv_bfloat16 g_zthi1[CNUM*NKTOT];
__device__ __align__(16) __nv_bfloat16 g_ztlo1[CNUM*NKTOT];
__device__ __align__(16) __nv_bfloat16 g_zthi2[CNUM*NKTOT];
__device__ __align__(16) __nv_bfloat16 g_ztlo2[CNUM*NKTOT];
__device__ __align__(16) float g_h [PNUM*CNUM];
__device__ __align__(16) float g_xl[PNUM*CNUM];
__device__ float g_q2[PNUM];
__device__ float g_zn[512];
__device__ float g_pm[128*CNUM];
__device__ float g_pd[128];
__device__ float g_pv[128];
__device__ float g_mu[CNUM];
__device__ float g_sc[8];

// ---------------- PTX helpers (baseline compute_103-safe) ----------------
__device__ __forceinline__ uint32_t smem_u32(const void* p) {
    uint32_t a;
    asm("{ .reg .u64 t; cvta.to.shared.u64 t, %1; cvt.u32.u64 %0, t; }" : "=r"(a) : "l"(p));
    return a;
}
__device__ __forceinline__ void cpa16(uint32_t dst, const void* src) {
    asm volatile("cp.async.cg.shared.global [%0], [%1], 16;" :: "r"(dst), "l"(src) : "memory");
}
__device__ __forceinline__ void cp_commit() {
    asm volatile("cp.async.commit_group;" ::: "memory");
}
template<int N>
__device__ __forceinline__ void cp_wait() {
    asm volatile("cp.async.wait_group %0;" :: "n"(N) : "memory");
}
__device__ __forceinline__ void ldsm4(uint32_t* r, uint32_t addr) {
    asm volatile("ldmatrix.sync.aligned.m8n8.x4.shared.b16 {%0,%1,%2,%3}, [%4];"
        : "=r"(r[0]), "=r"(r[1]), "=r"(r[2]), "=r"(r[3]) : "r"(addr));
}
__device__ __forceinline__ void mma16816(float* d, const uint32_t* a, const uint32_t* b) {
    asm volatile("mma.sync.aligned.m16n8k16.row.col.f32.bf16.bf16.f32 "
        "{%0,%1,%2,%3}, {%4,%5,%6,%7}, {%8,%9}, {%0,%1,%2,%3};"
        : "+f"(d[0]), "+f"(d[1]), "+f"(d[2]), "+f"(d[3])
        : "r"(a[0]), "r"(a[1]), "r"(a[2]), "r"(a[3]), "r"(b[0]), "r"(b[1]));
}

// swizzled physical offset within a [rows][32 bf16] tile (row = 64B, chunk = 16B)
__device__ __forceinline__ uint32_t swz(int r, int c) {
    return (uint32_t)(((r >> 1) << 7) | (((((r & 1) << 2) | c) ^ ((r >> 1) & 7)) << 4));
}

// ---------------- reductions ----------------
__device__ __forceinline__ float warpSum(float v) {
#pragma unroll
    for (int o = 16; o > 0; o >>= 1) v += __shfl_xor_sync(0xffffffffu, v, o);
    return v;
}
template<int K>
__device__ __forceinline__ void blockReduceK(float* v, float* sbuf) {
    int tid = threadIdx.x, lane = tid & 31, wid = tid >> 5;
#pragma unroll
    for (int i = 0; i < K; i++) {
        float x = v[i];
#pragma unroll
        for (int o = 16; o > 0; o >>= 1) x += __shfl_down_sync(0xffffffffu, x, o);
        if (lane == 0) sbuf[i*8 + wid] = x;
    }
    __syncthreads();
    if (tid == 0) {
#pragma unroll
        for (int i = 0; i < K; i++) {
            float s = sbuf[i*8];
            for (int w = 1; w < 8; w++) s += sbuf[i*8 + w];
            sbuf[i*8] = s;
        }
    }
    __syncthreads();
#pragma unroll
    for (int i = 0; i < K; i++) v[i] = sbuf[i*8];
    __syncthreads();
}

// ---------------- bf16 split store ----------------
union BU { uint4 u; __nv_bfloat16 h[8]; };
__device__ __forceinline__ void store_split8(size_t base, const float* v) {
    BU hi, lo;
#pragma unroll
    for (int i = 0; i < 8; i++) {
        __nv_bfloat16 h = __float2bfloat16(v[i]);
        hi.h[i] = h;
        lo.h[i] = __float2bfloat16(v[i] - __bfloat162float(h));
    }
    *(uint4*)(g_vhi + base) = hi.u;
    *(uint4*)(g_vlo + base) = lo.u;
}

// ---------------- zero padded borders ----------------
__global__ void zb_kernel() {
    int wid = threadIdx.x >> 5, lid = threadIdx.x & 31;
    int p = blockIdx.x * 8 + wid;
    if (p >= PADP) return;
    int pp = p % 1156, hh = pp / 34, ww = pp % 34;
    if (hh == 0 || hh == 33 || ww == 0 || ww == 33) {
        size_t base = (size_t)p * 256 + lid * 8;
        uint4 z = make_uint4(0u, 0u, 0u, 0u);
        *(uint4*)(g_vhi + base) = z;
        *(uint4*)(g_vlo + base) = z;
    }
}

// ---------------- z column norms ----------------
__global__ void zn_kernel(const float* __restrict__ z1, const float* __restrict__ z2) {
    int col = blockIdx.x;
    const float* z = (col < 256) ? z1 : z2;
    int j = col & 255;
    float s = 0.f;
    for (int k = threadIdx.x; k < NKTOT; k += 64) {
        float w = z[k*256 + j];
        s += w*w;
    }
#pragma unroll
    for (int o = 16; o > 0; o >>= 1) s += __shfl_down_sync(0xffffffffu, s, o);
    __shared__ float sb[2];
    if ((threadIdx.x & 31) == 0) sb[threadIdx.x >> 5] = s;
    __syncthreads();
    if (threadIdx.x == 0) g_zn[col] = sqrtf(fmaxf(sb[0] + sb[1], EPSF));
}

// ---------------- z split + transpose: z[K,N] fp32 -> zT hi/lo [N,K] bf16 ----------------
__global__ void zsplit_kernel(const float* __restrict__ z1, const float* __restrict__ z2) {
    __shared__ float t[32][33];
    const float* z = blockIdx.z ? z2 : z1;
    __nv_bfloat16* oh = blockIdx.z ? g_zthi2 : g_zthi1;
    __nv_bfloat16* ol = blockIdx.z ? g_ztlo2 : g_ztlo1;
    int kb = blockIdx.x * 32, nb = blockIdx.y * 32;
    int tx = threadIdx.x, ty = threadIdx.y;
#pragma unroll
    for (int i = 0; i < 4; i++)
        t[ty + i*8][tx] = z[(size_t)(kb + ty + i*8)*256 + nb + tx];
    __syncthreads();
#pragma unroll
    for (int i = 0; i < 4; i++) {
        int n = nb + ty + i*8, k = kb + tx;
        float v = t[tx][ty + i*8];
        __nv_bfloat16 h = __float2bfloat16(v);
        oh[(size_t)n*NKTOT + k] = h;
        ol[(size_t)n*NKTOT + k] = __float2bfloat16(v - __bfloat162float(h));
    }
}

// ---------------- xT: x NCHW -> g_xl [p][c] (both sides coalesced) ----------------
__global__ void xT_kernel(const float* __restrict__ x) {
    __shared__ float t[32][33];
    int hw0 = blockIdx.x * 32, c0 = blockIdx.y * 32, b = blockIdx.z;
    int tx = threadIdx.x, ty = threadIdx.y;
#pragma unroll
    for (int i = 0; i < 4; i++)
        t[ty + i*8][tx] = x[(size_t)(b*256 + c0 + ty + i*8)*1024 + hw0 + tx];
    __syncthreads();
#pragma unroll
    for (int i = 0; i < 4; i++)
        g_xl[(size_t)(b*1024 + hw0 + ty + i*8)*256 + c0 + tx] = t[tx][ty + i*8];
}

// ---------------- pre2: coalesced x read -> padded v hi/lo + q2 ----------------
__global__ void pre2_kernel(const float* __restrict__ x, float scale) {
    __shared__ float sx[256][33];
    int tid = threadIdx.x, lane = tid & 31, w8 = tid >> 5;
    int p0 = blockIdx.x * 32;
    int b = p0 >> 10, hw0 = p0 & 1023;
#pragma unroll 8
    for (int i = 0; i < 32; i++) {
        int c = i*8 + w8;
        sx[c][lane] = x[(size_t)(b*256 + c)*1024 + hw0 + lane];
    }
    __syncthreads();
#pragma unroll
    for (int pp = 0; pp < 4; pp++) {
        int pl = w8*4 + pp;
        int p = p0 + pl;
        int h = (p >> 5) & 31, w = p & 31;
        float xv[8];
#pragma unroll
        for (int i = 0; i < 8; i++) xv[i] = sx[lane*8 + i][pl];
        float q = 0.f;
#pragma unroll
        for (int i = 0; i < 8; i++) q += xv[i]*xv[i];
        float n2 = warpSum(q);
        float n = sqrtf(fmaxf(n2, EPSF));
        float f = atanhf(fminf(n, CLIP1)) / n * scale;
        float vv[8];
#pragma unroll
        for (int i = 0; i < 8; i++) vv[i] = f * xv[i];
        size_t base = ((size_t)(b*1156 + (h+1)*34 + (w+1)))*256 + lane*8;
        store_split8(base, vv);
        if (lane == 0) g_q2[p] = f*f*n2;
    }
}

// ---------------- per-pixel s = lam*alpha from 3x3 q2 sums (inline device fn) ----------------
__device__ __forceinline__ float s_from_q2(int p) {
    int h = (p >> 5) & 31, w = p & 31;
    float np2 = 0.f;
#pragma unroll
    for (int dy = -1; dy <= 1; dy++)
#pragma unroll
        for (int dx = -1; dx <= 1; dx++) {
            int sh = h + dy, sw = w + dx;
            if ((unsigned)sh < 32u && (unsigned)sw < 32u) np2 += g_q2[p + dy*32 + dx];
        }
    float np = sqrtf(fmaxf(np2, EPSF));
    float th = tanhf(np);
    float uf = th / np;
    float un = th;
    if (un > MAXN) { uf *= MAXN/un; un = MAXN; }
    float lam = 2.0f / fmaxf(1.0f - un*un, EPSF);
    return lam * uf;
}

// ---------------- HMMA conv + fused Poincare-FC epilogue ----------------
// CTA: 128 pixels (M) x 256 outputs (N). 512 thr = 16 warps (4m x 4n), warp 32x64.
// K = 9 taps x 256 ch, bf16 split-3 (hi*hi + lo*hi + hi*lo), fp32 accum. BK=32, 3-stage.
__global__ void __launch_bounds__(512, 1) conv_mma(int which) {
    extern __shared__ __align__(16) char dsm[];
    uint32_t sbase = smem_u32(dsm);

    const __nv_bfloat16* zThi = which ? g_zthi2 : g_zthi1;
    const __nv_bfloat16* zTlo = which ? g_ztlo2 : g_ztlo1;
    int znoff = which ? 256 : 0;

    int tid = threadIdx.x, wid = tid >> 5, l = tid & 31;
    int p0 = blockIdx.x << 7;
    int b  = blockIdx.x >> 3;
    int h0 = (blockIdx.x & 7) << 2;

    // ---- loader precompute ----
    int lr = tid >> 2, lc = tid & 3;
    int aIdx0 = (b*1156 + (h0 + (lr >> 5) + 1)*34 + ((lr & 31) + 1))*256 + lc*8;
    uint32_t physA = swz(lr, lc);
    int bn0 = tid >> 2, bn1 = (tid + 512) >> 2;
    int bIdx0 = bn0*NKTOT + lc*8;
    int bIdx1 = bn1*NKTOT + ((tid + 512) & 3)*8;
    uint32_t physB0 = swz(bn0, lc);
    uint32_t physB1 = swz(bn1, (tid + 512) & 3);

    // ---- mma lane precompute ----
    int m0 = (wid & 3) << 5;
    int n0 = (wid >> 2) << 6;
    int mi = l >> 3;
    int rA = m0 + ((mi & 1) << 3) + (l & 7);
    uint32_t qA0 = swz(rA, mi >> 1);
    int rB = n0 + (((mi >> 1) & 1) << 3) + (l & 7);
    uint32_t qB0 = swz(rB, mi & 1);

    float acc[2][8][4];
#pragma unroll
    for (int i = 0; i < 2; i++)
#pragma unroll
        for (int j = 0; j < 8; j++)
#pragma unroll
            for (int k = 0; k < 4; k++) acc[i][j][k] = 0.f;

    auto load_chunk = [&](int kc, int stage) {
        int tap = kc >> 3;
        int dy = (tap * 11) >> 5;
        int dx = tap - dy*3;
        int cb = (kc & 7) << 5;
        int ad = ((dy - 1)*34 + (dx - 1))*256 + cb;
        int bd = tap*256 + cb;
        uint32_t st = sbase + stage*STAGE_BYTES;
        cpa16(st + physA,             g_vhi + (aIdx0 + ad));
        cpa16(st + 8192  + physA,     g_vlo + (aIdx0 + ad));
        cpa16(st + 16384 + physB0,    zThi + (bIdx0 + bd));
        cpa16(st + 32768 + physB0,    zTlo + (bIdx0 + bd));
        cpa16(st + 16384 + physB1,    zThi + (bIdx1 + bd));
        cpa16(st + 32768 + physB1,    zTlo + (bIdx1 + bd));
        cp_commit();
    };

    load_chunk(0, 0);
    load_chunk(1, 1);

    for (int kc = 0; kc < 72; kc++) {
        int stage = kc % 3;
        if (kc < 70) cp_wait<1>(); else cp_wait<0>();
        __syncthreads();
        if (kc + 2 < 72) load_chunk(kc + 2, (kc + 2) % 3);

        uint32_t sA_hi = sbase + stage*STAGE_BYTES;
        uint32_t sA_lo = sA_hi + 8192;
        uint32_t sB_hi = sA_hi + 16384;
        uint32_t sB_lo = sA_hi + 32768;

        uint32_t ah[8], al[8], bb[16];
#pragma unroll
        for (int ks = 0; ks < 2; ks++) {
            uint32_t kx = (uint32_t)(ks << 5);
            uint32_t qa = qA0 ^ kx, qb = qB0 ^ kx;
            ldsm4(ah,     sA_hi + qa);
            ldsm4(ah + 4, sA_hi + qa + 1024);
            ldsm4(al,     sA_lo + qa);
            ldsm4(al + 4, sA_lo + qa + 1024);
#pragma unroll
            for (int j = 0; j < 4; j++) ldsm4(bb + j*4, sB_hi + qb + j*1024);
            // hihi + lohi (B_hi in regs)
#pragma unroll
            for (int nf = 0; nf < 8; nf++) {
#pragma unroll
                for (int mf = 0; mf < 2; mf++) mma16816(acc[mf][nf], ah + mf*4, bb + nf*2);
#pragma unroll
                for (int mf = 0; mf < 2; mf++) mma16816(acc[mf][nf], al + mf*4, bb + nf*2);
            }
            // hilo (B_lo reload, A_hi still in regs)
#pragma unroll
            for (int j = 0; j < 4; j++) ldsm4(bb + j*4, sB_lo + qb + j*1024);
#pragma unroll
            for (int nf = 0; nf < 8; nf++)
#pragma unroll
                for (int mf = 0; mf < 2; mf++) mma16816(acc[mf][nf], ah + mf*4, bb + nf*2);
        }
    }
    __syncthreads();   // all warps done reading stages before ybuf overwrites smem

    // ---- fused Poincare-FC epilogue ----
    float* ybuf = (float*)dsm;
    int row0 = m0 + (l >> 2);
    int col0 = n0 + ((l & 3) << 1);
    float sr[2][2];
#pragma unroll
    for (int mf = 0; mf < 2; mf++)
#pragma unroll
        for (int hf = 0; hf < 2; hf++)
            sr[mf][hf] = s_from_q2(p0 + row0 + mf*16 + hf*8);
    float2 zn2[8];
#pragma unroll
    for (int nf = 0; nf < 8; nf++)
        zn2[nf] = *(const float2*)&g_zn[znoff + col0 + nf*8];

#pragma unroll
    for (int mf = 0; mf < 2; mf++)
#pragma unroll
        for (int nf = 0; nf < 8; nf++)
#pragma unroll
            for (int hf = 0; hf < 2; hf++) {
                float s = sr[mf][hf];
                float z0 = zn2[nf].x, z1 = zn2[nf].y;
                float a0 = acc[mf][nf][hf*2], a1 = acc[mf][nf][hf*2 + 1];
                float y0 = sinhf(2.0f*z0*asinhf(a0*s/z0));
                float y1 = sinhf(2.0f*z1*asinhf(a1*s/z1));
                int r = row0 + mf*16 + hf*8;
                *(float2*)&ybuf[r*YST + col0 + nf*8] = make_float2(y0, y1);
            }
    __syncthreads();

    // row reduction + scale + write g_h
    {
        int row = tid >> 2, q = tid & 3;
        const float4* yr = (const float4*)(ybuf + row*YST + q*64);
        float tot = 0.f;
#pragma unroll
        for (int i = 0; i < 16; i++) {
            float4 v = yr[i];
            tot += v.x*v.x + v.y*v.y + v.z*v.z + v.w*v.w;
        }
        tot += __shfl_xor_sync(0xffffffffu, tot, 1);
        tot += __shfl_xor_sync(0xffffffffu, tot, 2);
        float inv = 1.0f / (1.0f + sqrtf(1.0f + tot));
        float4* dst = (float4*)(g_h + (size_t)(p0 + row)*256 + q*64);
#pragma unroll
        for (int i = 0; i < 16; i++) {
            float4 v = yr[i];
            v.x *= inv; v.y *= inv; v.z *= inv; v.w *= inv;
            dst[i] = v;
        }
    }
}

// ---------------- BN phase 1: partial sums (warp-per-pixel) ----------------
__global__ void bnred_w() {
    __shared__ float sm[8][256];
    __shared__ float sd[8];
    int wid = threadIdx.x >> 5, lid = threadIdx.x & 31;
    int p0 = blockIdx.x * 128;
    float accm[8] = {0,0,0,0,0,0,0,0};
    float accd = 0.f;
    for (int i = 0; i < 16; i++) {
        int p = p0 + wid*16 + i;
        const float4* row = (const float4*)(g_h + (size_t)p*256 + lid*8);
        float4 a = row[0], c = row[1];
        float v[8] = {a.x,a.y,a.z,a.w,c.x,c.y,c.z,c.w};
        float q = 0.f;
#pragma unroll
        for (int j = 0; j < 8; j++) q += v[j]*v[j];
        float n2 = warpSum(q);
        float lam = 2.0f / fmaxf(1.0f - n2, EPSF);
#pragma unroll
        for (int j = 0; j < 8; j++) accm[j] += lam * v[j];
        accd += lam - 1.0f;
    }
#pragma unroll
    for (int j = 0; j < 8; j++) sm[wid][lid*8 + j] = accm[j];
    if (lid == 0) sd[wid] = accd;
    __syncthreads();
    int c = threadIdx.x;
    float s = 0.f;
    for (int w = 0; w < 8; w++) s += sm[w][c];
    g_pm[blockIdx.x*256 + c] = s;
    if (c == 0) {
        float d = 0.f;
        for (int w = 0; w < 8; w++) d += sd[w];
        g_pd[blockIdx.x] = d;
    }
}

// ---------------- BN phase 2: gyromidpoint + scalars ----------------
__global__ void bnmu_kernel(const float* __restrict__ bias) {
    __shared__ float sb[24];
    int c = threadIdx.x;
    float msum = 0.f;
    for (int g = 0; g < 128; g++) msum += g_pm[g*256 + c];
    float dv = (c < 128) ? g_pd[c] : 0.f;
    float r1[1] = { dv };
    blockReduceK<1>(r1, sb);
    float den = fmaxf(r1[0], EPSF);
    float m = msum / den;
    float r2[1] = { m*m };
    blockReduceK<1>(r2, sb);
    float nm = sqrtf(fmaxf(r2[0], EPSF));
    float fac = tanhf(0.5f * atanhf(fminf(nm, CLIP1))) / nm;
    float muc = fac * m;
    g_mu[c] = muc;
    float bc = bias[c];
    float r3[3] = { muc*muc, bc*bc, bc*muc };
    blockReduceK<3>(r3, sb);
    if (c == 0) {
        float mu2 = r3[0], b2 = r3[1], bm = r3[2];
        g_sc[0] = mu2;
        g_sc[1] = 2.0f / fmaxf(1.0f - mu2, EPSF);
        g_sc[2] = b2;
        g_sc[3] = 2.0f / fmaxf(1.0f - b2, EPSF);
        g_sc[4] = bm;
    }
}

// ---------------- BN phase 3: partial variance (warp-per-pixel) ----------------
__global__ void bnvar_w() {
    __shared__ float sv[8];
    int wid = threadIdx.x >> 5, lid = threadIdx.x & 31;
    int p0 = blockIdx.x * 128;
    float mu8[8];
#pragma unroll
    for (int j = 0; j < 8; j++) mu8[j] = g_mu[lid*8 + j];
    float mu2 = g_sc[0];
    float acc = 0.f;
    for (int i = 0; i < 16; i++) {
        int p = p0 + wid*16 + i;
        const float4* row = (const float4*)(g_h + (size_t)p*256 + lid*8);
        float4 a = row[0], cc = row[1];
        float v[8] = {a.x,a.y,a.z,a.w,cc.x,cc.y,cc.z,cc.w};
        float q1 = 0.f, q2 = 0.f;
#pragma unroll
        for (int j = 0; j < 8; j++) { q1 += v[j]*v[j]; q2 += v[j]*mu8[j]; }
        float xp2 = warpSum(q1);
        float ip  = warpSum(q2);
        float A = 1.0f - 2.0f*ip + mu2;
        float B = 1.0f - xp2;
        float nn = fmaxf(A*A*xp2 - 2.0f*A*B*ip + B*B*mu2, 0.f);
        float den = fmaxf(1.0f - 2.0f*ip + xp2*mu2, EPSF);
        float nr = sqrtf(fmaxf(nn/(den*den), EPSF));
        float dd = 2.0f * atanhf(fminf(nr, CLIP1));
        acc += dd*dd;
    }
    if (lid == 0) sv[wid] = acc;
    __syncthreads();
    if (threadIdx.x == 0) {
        float s = 0.f;
        for (int w = 0; w < 8; w++) s += sv[w];
        g_pv[blockIdx.x] = s;
    }
}

// ---------------- BN phase 4: finalize rstd ----------------
__global__ void bnfin_kernel(const float* __restrict__ weight) {
    int tid = threadIdx.x;
    float v = g_pv[tid];
#pragma unroll
    for (int o = 16; o > 0; o >>= 1) v += __shfl_down_sync(0xffffffffu, v, o);
    __shared__ float sb[4];
    if ((tid & 31) == 0) sb[tid >> 5] = v;
    __syncthreads();
    if (tid == 0) {
        float var = (sb[0] + sb[1] + sb[2] + sb[3]) / 16384.0f;
        g_sc[5] = sqrtf(weight[0] / fmaxf(var, EPSF));
    }
}

// ---------------- shared BN point transform (warp version) ----------------
__device__ __forceinline__ float bn_point_w(const float* xv, const float* mu8, const float* b8,
                                            float* hc) {
    float mu2 = g_sc[0], lam_mu = g_sc[1], b2 = g_sc[2], lam_b = g_sc[3],
          bm = g_sc[4], rstd = g_sc[5];
    float s0 = 0.f, s1 = 0.f, s2 = 0.f;
#pragma unroll
    for (int i = 0; i < 8; i++) { s0 += xv[i]*xv[i]; s1 += mu8[i]*xv[i]; s2 += b8[i]*xv[i]; }
    float xp2 = warpSum(s0), ip = warpSum(s1), bx = warpSum(s2);
    float A  = 1.0f - 2.0f*ip + xp2;
    float Bc = 1.0f - mu2;
    float den = fmaxf(1.0f - 2.0f*ip + mu2*xp2, EPSF);
    float nd2 = fmaxf(A*A*mu2 - 2.0f*A*Bc*ip + Bc*Bc*xp2, 0.f) / (den*den);
    float nd = sqrtf(fmaxf(nd2, EPSF));
    float cv = (2.0f/lam_mu) * atanhf(fminf(nd, CLIP1)) / nd;
    float uw = cv * (Bc*bx - A*bm) / den;
    float vw = cv * (A*mu2 - Bc*ip) / den;
    float av  = -uw*mu2 - vw - 2.0f*bm*vw;
    float bv2 = -vw*b2 + uw;
    float dgy = fmaxf(1.0f - 2.0f*bm + b2*mu2, EPSF);
    float fac = (lam_mu / lam_b) * rstd;
    float uc[8];
    float t0 = 0.f, t1 = 0.f;
#pragma unroll
    for (int i = 0; i < 8; i++) {
        float vc = cv * (Bc*xv[i] - A*mu8[i]) / den;
        uc[i] = (vc + 2.0f*(av*b8[i] - bv2*mu8[i]) / dgy) * fac;
        t0 += uc[i]*uc[i];
        t1 += b8[i]*uc[i];
    }
    float u2 = warpSum(t0), bu = warpSum(t1);
    float nu = sqrtf(fmaxf(u2, EPSF));
    float tf = tanhf(0.5f * lam_b * nu) / nu;
    float s2m = tf*tf*u2;
    float bs  = tf*bu;
    float A3 = 1.0f + 2.0f*bs + s2m, B3 = 1.0f - b2;
    float den3 = fmaxf(1.0f + 2.0f*bs + b2*s2m, EPSF);
#pragma unroll
    for (int i = 0; i < 8; i++) hc[i] = (A3*b8[i] + B3*tf*uc[i]) / den3;
    float nh2 = fmaxf(A3*A3*b2 + 2.0f*A3*B3*bs + B3*B3*s2m, 0.f) / (den3*den3);
    float nh = sqrtf(fmaxf(nh2, EPSF));
    if (nh > MAXN) {
        float q = MAXN / nh;
#pragma unroll
        for (int i = 0; i < 8; i++) hc[i] *= q;
        nh = MAXN;
    }
    return nh;
}

// ---------------- BN apply + hrelu + pre-for-conv2 (warp-per-pixel) ----------------
__global__ void bnapply_w(const float* __restrict__ bias, float scale) {
    int wid = threadIdx.x >> 5, lid = threadIdx.x & 31;
    int p = blockIdx.x * 8 + wid;
    int b = p >> 10, h = (p >> 5) & 31, w = p & 31;
    const float4* row = (const float4*)(g_h + (size_t)p*256 + lid*8);
    float4 a = row[0], cc = row[1];
    float xv[8] = {a.x,a.y,a.z,a.w,cc.x,cc.y,cc.z,cc.w};
    float mu8[8], b8[8];
#pragma unroll
    for (int j = 0; j < 8; j++) { mu8[j] = g_mu[lid*8 + j]; b8[j] = bias[lid*8 + j]; }
    float hc[8];
    float nh = bn_point_w(xv, mu8, b8, hc);
    float lf = atanhf(fminf(nh, CLIP1)) / nh;
    float rc[8];
    float q = 0.f;
#pragma unroll
    for (int i = 0; i < 8; i++) { rc[i] = fmaxf(lf*hc[i], 0.f); q += rc[i]*rc[i]; }
    float rs = warpSum(q);
    float nr = sqrtf(fmaxf(rs, EPSF));
    float ef = tanhf(nr) / nr;
    float nhr = sqrtf(fmaxf(ef*ef*rs, EPSF));
    float adj = 1.0f;
    if (nhr > MAXN) { adj = MAXN/nhr; nhr = MAXN; }
    float f3 = atanhf(fminf(nhr, CLIP1)) / nhr * scale;
    float vv[8];
#pragma unroll
    for (int i = 0; i < 8; i++) vv[i] = f3 * ef * adj * rc[i];
    size_t base = ((size_t)(b*1156 + (h+1)*34 + (w+1)))*256 + lid*8;
    store_split8(base, vv);
    if (lid == 0) g_q2[p] = f3*f3*nhr*nhr;
}

// ---------------- BN2 apply + residual + hrelu + staged NCHW out ----------------
__global__ void final2_kernel(const float* __restrict__ bias, float* __restrict__ out) {
    __shared__ float so[256][33];
    int tid = threadIdx.x, lane = tid & 31, w8 = tid >> 5;
    int p0 = blockIdx.x * 32;
    int b = p0 >> 10, hw0 = p0 & 1023;
    float mu8[8], b8[8];
#pragma unroll
    for (int j = 0; j < 8; j++) { mu8[j] = g_mu[lane*8 + j]; b8[j] = bias[lane*8 + j]; }
#pragma unroll
    for (int pp = 0; pp < 4; pp++) {
        int pl = w8*4 + pp;
        int p = p0 + pl;
        const float4* row = (const float4*)(g_h + (size_t)p*256 + lane*8);
        float4 a = row[0], cc = row[1];
        float xv[8] = {a.x,a.y,a.z,a.w,cc.x,cc.y,cc.z,cc.w};
        float hc[8];
        float nh = bn_point_w(xv, mu8, b8, hc);
        const float4* rrow = (const float4*)(g_xl + (size_t)p*256 + lane*8);
        float4 r0 = rrow[0], r1 = rrow[1];
        float res[8] = {r0.x,r0.y,r0.z,r0.w,r1.x,r1.y,r1.z,r1.w};
        float q1 = 0.f, q2 = 0.f;
#pragma unroll
        for (int i = 0; i < 8; i++) { q1 += res[i]*res[i]; q2 += hc[i]*res[i]; }
        float y2 = warpSum(q1), xy = warpSum(q2);
        float x2 = nh*nh;
        float A4 = 1.0f + 2.0f*xy + y2, B4 = 1.0f - x2;
        float den4 = fmaxf(1.0f + 2.0f*xy + x2*y2, EPSF);
        float hm[8];
#pragma unroll
        for (int i = 0; i < 8; i++) hm[i] = (A4*hc[i] + B4*res[i]) / den4;
        float nm2 = fmaxf(A4*A4*x2 + 2.0f*A4*B4*xy + B4*B4*y2, 0.f) / (den4*den4);
        float nmv = sqrtf(fmaxf(nm2, EPSF));
        float lf = atanhf(fminf(nmv, CLIP1)) / nmv;
        float rc[8];
        float q = 0.f;
#pragma unroll
        for (int i = 0; i < 8; i++) { rc[i] = fmaxf(lf*hm[i], 0.f); q += rc[i]*rc[i]; }
        float rs = warpSum(q);
        float nr = sqrtf(fmaxf(rs, EPSF));
        float ef = tanhf(nr) / nr;
        float nhr = sqrtf(fmaxf(ef*ef*rs, EPSF));
        float adj = (nhr > MAXN) ? MAXN/nhr : 1.0f;
#pragma unroll
        for (int i = 0; i < 8; i++) so[lane*8 + i][pl] = ef * adj * rc[i];
    }
    __syncthreads();
#pragma unroll 8
    for (int i = 0; i < 32; i++) {
        int c = i*8 + w8;
        out[(size_t)(b*256 + c)*1024 + hw0 + lane] = so[c][lane];
    }
}

// ---------------- launcher ----------------
extern "C" void kernel_launch(void* const* d_in, const int* in_sizes, int n_in,
                              void* d_out, int out_size) {
    const float* x  = (const float*)d_in[0];
    const float* z1 = (const float*)d_in[1];
    const float* z2 = (const float*)d_in[2];
    const float* w1 = (const float*)d_in[3];
    const float* b1 = (const float*)d_in[4];
    const float* w2 = (const float*)d_in[5];
    const float* b2 = (const float*)d_in[6];
    float* out = (float*)d_out;

    // scale = Beta(1152, 0.5) / Beta(128, 0.5)
    double lg = lgamma(1152.0) - lgamma(1152.5) - lgamma(128.0) + lgamma(128.5);
    float scale = (float)exp(lg);

    static int smem_set = 0;
    if (!smem_set) {
        cudaFuncSetAttribute(conv_mma, cudaFuncAttributeMaxDynamicSharedMemorySize, CONV_SMEM);
        smem_set = 1;
    }

    zb_kernel<<<(PADP + 7)/8, 256>>>();
    zn_kernel<<<512, 64>>>(z1, z2);
    zsplit_kernel<<<dim3(72, 8, 2), dim3(32, 8)>>>(z1, z2);
    xT_kernel<<<dim3(32, 8, 16), dim3(32, 8)>>>(x);
    pre2_kernel<<<PNUM/32, 256>>>(x, scale);
    conv_mma<<<128, 512, CONV_SMEM>>>(0);

    bnred_w<<<128, 256>>>();
    bnmu_kernel<<<1, 256>>>(b1);
    bnvar_w<<<128, 256>>>();
    bnfin_kernel<<<1, 128>>>(w1);
    bnapply_w<<<PNUM/8, 256>>>(b1, scale);

    conv_mma<<<128, 512, CONV_SMEM>>>(1);

    bnred_w<<<128, 256>>>();
    bnmu_kernel<<<1, 256>>>(b2);
    bnvar_w<<<128, 256>>>();
    bnfin_kernel<<<1, 128>>>(w2);
    final2_kernel<<<PNUM/32, 256>>>(b2, out);
}